// round 8
// baseline (speedup 1.0000x reference)
#include <cuda_runtime.h>

// Problem constants
#define B_     8
#define DIM    64
#define HID    128
#define HH     192
#define WW     192
#define HW     (HH*WW)          // 36864
#define TS     16
#define PAD    18
#define NPIX   (PAD*PAD)        // 324
#define NTILX  12
#define NTILY  12
#define NTILES (NTILX*NTILY*B_) // 1152
#define NT     256
// Phase-1 register tiling: 12 px x 8 hid-pairs per thread
#define PXG    12
#define NPXG   (NPIX/PXG)       // 27
#define PPT    8                // hid-pairs per thread
#define NPB    (64/PPT)         // 8 pairblocks
#define P1JOBS (NPXG*NPB)       // 216
#define CCH    16               // input channels staged per chunk
// Phase-2: y-chunks of 8 hid-pairs
#define YCH    8

typedef unsigned long long ull;

__device__ __forceinline__ ull ffma2(ull a, ull b, ull c) {
    ull d;
    asm("fma.rn.f32x2 %0, %1, %2, %3;" : "=l"(d) : "l"(a), "l"(b), "l"(c));
    return d;
}
__device__ __forceinline__ ull mul2(ull a, ull b) {
    ull d;
    asm("mul.rn.f32x2 %0, %1, %2;" : "=l"(d) : "l"(a), "l"(b));
    return d;
}
__device__ __forceinline__ ull pack2(float x) {
    ull r;
    asm("mov.b64 %0, {%1, %1};" : "=l"(r) : "f"(x));
    return r;
}
__device__ __forceinline__ ull pack2b(float lo, float hi) {
    ull r;
    asm("mov.b64 %0, {%1, %2};" : "=l"(r) : "f"(lo), "f"(hi));
    return r;
}
__device__ __forceinline__ void unpack2(ull v, float& lo, float& hi) {
    asm("mov.b64 {%0, %1}, %2;" : "=f"(lo), "=f"(hi) : "l"(v));
}

// Scratch + barrier state (zero-initialized; no device mallocs allowed)
__device__ float g_xmean[B_*DIM];
__device__ float g_ker[B_*HID*9];
__device__ unsigned g_bar1, g_bar2, g_done;

__device__ __forceinline__ void gbar(unsigned* bar, unsigned NB, int tid) {
    if (tid == 0) {
        __threadfence();
        atomicAdd(bar, 1u);
        while (atomicAdd(bar, 0u) < NB) __nanosleep(128);
    }
    __syncthreads();
    __threadfence();
}

extern __shared__ float smem[];

// Dynamic SMEM layout (float offsets):
//   sh_w    [0      .. 8192)   phase1: w_in^T [c][hid] / phase2: w_out [hid][o]
//   sh_ker2 [8192   .. 9344)   576 ull paired dyn kernels
//   sh_bin  [9344   .. 9472)
//   sh_bout [9472   .. 9536)
//   sh_stg  [9536   .. 14720)  x-chunk (16c x 324) OR y-chunk (8 pairs x 256 ull)
//   sh_h    [14720  .. 56192)  64 hid-pairs x 324 px (ull)
// total 56192 floats = 224,768 B
__global__ __launch_bounds__(NT, 1)
void k_all(const float* __restrict__ x,
           const float* __restrict__ w_in,  const float* __restrict__ b_in,
           const float* __restrict__ wg1,   const float* __restrict__ bg1,
           const float* __restrict__ wg2,   const float* __restrict__ bg2,
           const float* __restrict__ w_out, const float* __restrict__ b_out,
           float* __restrict__ out) {
    const int tid = threadIdx.x;
    const unsigned NB = gridDim.x;

    // =================== Phase A: per-(b,c) spatial means ===================
    {
        __shared__ float redw[8];
        for (int bc = blockIdx.x; bc < B_*DIM; bc += (int)NB) {
            const float4* p = (const float4*)(x + (size_t)bc * HW);
            float s = 0.f;
            #pragma unroll 4
            for (int i = tid; i < HW/4; i += NT) {
                float4 v = p[i];
                s += (v.x + v.y) + (v.z + v.w);
            }
            #pragma unroll
            for (int o = 16; o; o >>= 1) s += __shfl_down_sync(0xffffffffu, s, o);
            if ((tid & 31) == 0) redw[tid >> 5] = s;
            __syncthreads();
            if (tid < 32) {
                s = (tid < 8) ? redw[tid] : 0.f;
                #pragma unroll
                for (int o = 4; o; o >>= 1) s += __shfl_down_sync(0xffffffffu, s, o);
                if (tid == 0) g_xmean[bc] = s * (1.0f / (float)HW);
            }
            __syncthreads();
        }
    }
    gbar(&g_bar1, NB, tid);

    // =================== Phase B: dynamic kernel generation =================
    if (blockIdx.x < B_) {
        const int b = blockIdx.x;
        __shared__ float xm[DIM], g0[HID], g1[HID];
        if (tid < DIM) xm[tid] = g_xmean[b*DIM + tid];
        __syncthreads();
        if (tid < HID) {
            float s = b_in[tid];
            #pragma unroll 8
            for (int c = 0; c < DIM; c++) s = fmaf(w_in[tid*DIM + c], xm[c], s);
            g0[tid] = s;   // == spatial mean of h[b, tid] (mean is linear)
        }
        __syncthreads();
        if (tid < HID) {
            float s = bg1[tid];
            #pragma unroll 8
            for (int c = 0; c < HID; c++) s = fmaf(wg1[tid*HID + c], g0[c], s);
            g1[tid] = s > 0.f ? s : 0.f;
        }
        __syncthreads();
        if (tid < HID) {
            #pragma unroll
            for (int tt = 0; tt < 9; tt++) {
                int row = tid*9 + tt;
                float s = bg2[row];
                #pragma unroll 8
                for (int c = 0; c < HID; c++) s = fmaf(wg2[row*HID + c], g1[c], s);
                g_ker[b*HID*9 + row] = s;
            }
        }
    }
    gbar(&g_bar2, NB, tid);

    // ======================= Phase C: fused main loop =======================
    float* sh_w    = smem;
    ull*   sh_ker2 = (ull*)(smem + 8192);
    float* sh_bin  = smem + 9344;
    float* sh_bout = smem + 9472;
    float* sh_stg  = smem + 9536;
    ull*   sh_y    = (ull*)sh_stg;
    ull*   sh_h    = (ull*)(smem + 14720);
    const ull* sh_wull = (const ull*)smem;

    if (tid < HID) sh_bin[tid]  = b_in[tid];
    if (tid < 64)  sh_bout[tid] = b_out[tid];

    // phase-1 job decode (tid < 216 active)
    const int pxg = tid >> 3;        // 0..31 (27 used)
    const int pb  = tid & 7;
    const int px0 = pxg * PXG;
    // phase-2b decode
    const int pxq = tid >> 2;        // 0..63
    const int ob  = tid & 3;

    const ull ABSM = 0x7fffffff7fffffffULL;
    const ull C55 = pack2(0.55f), C45 = pack2(0.45f);

    #pragma unroll 1
    for (int t = blockIdx.x; t < NTILES; t += (int)NB) {
        const int b   = t / (NTILX*NTILY);
        const int r   = t - b*(NTILX*NTILY);
        const int ty0 = (r / NTILX)*TS;
        const int tx0 = (r % NTILX)*TS;
        const float* xb = x + (size_t)b * DIM * HW;

        __syncthreads();   // previous tile finished reading sh_w / sh_h

        // stage w_in^T [c][hid] + this sample's paired kernels
        for (int i = tid; i < HID*DIM; i += NT) {
            int o = i >> 6, c = i & 63;
            sh_w[c*HID + o] = w_in[i];
        }
        {
            const float* kb = g_ker + b*HID*9;
            for (int i = tid; i < 64*9; i += NT) {
                int p = i / 9, tt = i - p*9;
                sh_ker2[i] = pack2b(kb[(2*p)*9 + tt], kb[(2*p+1)*9 + tt]);
            }
        }
        __syncthreads();

        // --------------- Phase 1: h GEMM, register-blocked -----------------
        ull acc[PXG][PPT];
        {
            const ull* bp = (const ull*)sh_bin + pb*PPT;
            ull bseg[PPT];
            #pragma unroll
            for (int j = 0; j < PPT; j++) bseg[j] = bp[j];
            #pragma unroll
            for (int k = 0; k < PXG; k++)
                #pragma unroll
                for (int j = 0; j < PPT; j++) acc[k][j] = bseg[j];
        }

        #pragma unroll 1
        for (int cc = 0; cc < DIM; cc += CCH) {
            // stage x chunk [16 c][324 px] with border zeros
            for (int i = tid; i < CCH*NPIX; i += NT) {
                int c  = i / NPIX, pp = i - c*NPIX;
                int py = pp / PAD, pxx = pp - py*PAD;
                int gy = ty0 + py - 1, gx = tx0 + pxx - 1;
                bool v = (gy >= 0) & (gy < HH) & (gx >= 0) & (gx < WW);
                sh_stg[c*NPIX + pp] = v ? __ldg(xb + (size_t)(cc + c)*HW + gy*WW + gx) : 0.f;
            }
            __syncthreads();

            if (tid < P1JOBS) {
                #pragma unroll 1
                for (int c = 0; c < CCH; c++) {
                    const float4* xs = (const float4*)(sh_stg + c*NPIX + px0);
                    float4 xa = xs[0], xb4 = xs[1], xc4 = xs[2];
                    const ulonglong2* wp =
                        (const ulonglong2*)(sh_wull + (size_t)(cc + c)*64 + pb*PPT);
                    ulonglong2 w01 = wp[0], w23 = wp[1], w45 = wp[2], w67 = wp[3];
                    ull w[PPT] = {w01.x, w01.y, w23.x, w23.y, w45.x, w45.y, w67.x, w67.y};
                    float xv[PXG] = {xa.x, xa.y, xa.z, xa.w,
                                     xb4.x, xb4.y, xb4.z, xb4.w,
                                     xc4.x, xc4.y, xc4.z, xc4.w};
                    #pragma unroll
                    for (int k = 0; k < PXG; k++) {
                        ull xx = pack2(xv[k]);
                        #pragma unroll
                        for (int j = 0; j < PPT; j++)
                            acc[k][j] = ffma2(w[j], xx, acc[k][j]);
                    }
                }
            }
            __syncthreads();   // before next chunk overwrites sh_stg
        }

        // store h (zero-masked at borders) + restage sh_w -> w_out [hid][o]
        if (tid < P1JOBS) {
            #pragma unroll
            for (int k = 0; k < PXG; k++) {
                int pp = px0 + k;
                int py = pp / PAD, pxx = pp - py*PAD;
                int gy = ty0 + py - 1, gx = tx0 + pxx - 1;
                bool v = (gy >= 0) & (gy < HH) & (gx >= 0) & (gx < WW);
                #pragma unroll
                for (int j = 0; j < PPT; j++)
                    sh_h[(pb*PPT + j)*NPIX + pp] = v ? acc[k][j] : 0ull;
            }
        }
        for (int i = tid; i < 64*HID; i += NT) {
            int o = i >> 7, hid = i & 127;
            sh_w[hid*64 + o] = w_out[i];
        }
        __syncthreads();

        // --------------- Phase 2: dw+leaky (2a) then projection (2b) -------
        ull pacc[4][8];
        {
            const ull* bop = (const ull*)sh_bout + ob*8;
            ull bs[8];
            #pragma unroll
            for (int j = 0; j < 8; j++) bs[j] = bop[j];
            #pragma unroll
            for (int k = 0; k < 4; k++)
                #pragma unroll
                for (int j = 0; j < 8; j++) pacc[k][j] = bs[j];
        }

        #pragma unroll 1
        for (int yc = 0; yc < 64; yc += YCH) {
            // 2a: y for pairs [yc, yc+8) over the 256 interior pixels
            #pragma unroll 1
            for (int s = 0; s < 8; s++) {
                int slot = tid + s*NT;           // 0..2047
                int p  = slot >> 8;              // 0..7
                int px = slot & 255;
                int ix = px & 15, iy = px >> 4;
                int ctr = (iy + 1)*PAD + ix + 1;
                int gp  = yc + p;
                const ull* hp = sh_h + gp*NPIX + ctr;
                const ull* kp = sh_ker2 + gp*9;
                ull sa;
                sa = mul2 (kp[0], hp[-PAD-1]);
                sa = ffma2(kp[1], hp[-PAD  ], sa);
                sa = ffma2(kp[2], hp[-PAD+1], sa);
                sa = ffma2(kp[3], hp[-1    ], sa);
                sa = ffma2(kp[4], hp[ 0    ], sa);
                sa = ffma2(kp[5], hp[ 1    ], sa);
                sa = ffma2(kp[6], hp[ PAD-1], sa);
                sa = ffma2(kp[7], hp[ PAD  ], sa);
                sa = ffma2(kp[8], hp[ PAD+1], sa);
                // LeakyReLU(0.1) packed: 0.55*s + 0.45*|s|
                sh_y[p*256 + px] = ffma2(sa & ABSM, C45, mul2(sa, C55));
            }
            __syncthreads();

            // 2b: projection, thread tile 4 px x 8 out-pairs
            #pragma unroll 2
            for (int p = 0; p < YCH; p++) {
                int gp = yc + p;
                const ulonglong2* yp = (const ulonglong2*)(sh_y + p*256 + pxq*4);
                ulonglong2 ya = yp[0], yb2 = yp[1];
                ull yv[4] = {ya.x, ya.y, yb2.x, yb2.y};
                const ulonglong2* wl = (const ulonglong2*)(sh_wull + (size_t)gp*64 + ob*8);
                const ulonglong2* wh = (const ulonglong2*)(sh_wull + (size_t)gp*64 + 32 + ob*8);
                ulonglong2 l01 = wl[0], l23 = wl[1], l45 = wl[2], l67 = wl[3];
                ulonglong2 h01 = wh[0], h23 = wh[1], h45 = wh[2], h67 = wh[3];
                ull wlo[8] = {l01.x, l01.y, l23.x, l23.y, l45.x, l45.y, l67.x, l67.y};
                ull whi[8] = {h01.x, h01.y, h23.x, h23.y, h45.x, h45.y, h67.x, h67.y};
                #pragma unroll
                for (int k = 0; k < 4; k++) {
                    float ylo, yhi;
                    unpack2(yv[k], ylo, yhi);
                    ull ylo2 = pack2(ylo), yhi2 = pack2(yhi);
                    #pragma unroll
                    for (int j = 0; j < 8; j++) {
                        pacc[k][j] = ffma2(wlo[j], ylo2, pacc[k][j]);
                        pacc[k][j] = ffma2(whi[j], yhi2, pacc[k][j]);
                    }
                }
            }
            __syncthreads();   // before next chunk overwrites sh_y
        }

        // store output: 4 px x 16 out-channels per thread
        {
            #pragma unroll
            for (int k = 0; k < 4; k++) {
                int px = pxq*4 + k;
                int ix = px & 15, iy = px >> 4;
                int gy = ty0 + iy, gx = tx0 + ix;
                float* op = out + (size_t)b * DIM * HW + gy*WW + gx;
                #pragma unroll
                for (int j = 0; j < 8; j++) {
                    int och = ob*16 + 2*j;
                    float lo, hi;
                    unpack2(pacc[k][j], lo, hi);
                    op[(size_t)och * HW]       = lo;
                    op[(size_t)(och + 1) * HW] = hi;
                }
            }
        }
    }

    // reset barrier state for the next graph replay
    if (tid == 0) {
        __threadfence();
        if (atomicAdd(&g_done, 1u) == NB - 1u) {
            atomicExch(&g_bar1, 0u);
            atomicExch(&g_bar2, 0u);
            atomicExch(&g_done, 0u);
        }
    }
}

// ---------------------------------------------------------------------------
extern "C" void kernel_launch(void* const* d_in, const int* in_sizes, int n_in,
                              void* d_out, int out_size) {
    const float* x     = (const float*)d_in[0];
    const float* w_in  = (const float*)d_in[1];
    const float* b_in  = (const float*)d_in[2];
    const float* wg1   = (const float*)d_in[3];
    const float* bg1   = (const float*)d_in[4];
    const float* wg2   = (const float*)d_in[5];
    const float* bg2   = (const float*)d_in[6];
    const float* w_out = (const float*)d_in[7];
    const float* b_out = (const float*)d_in[8];
    float* out = (float*)d_out;

    int dev = 0, nsm = 148;
    cudaGetDevice(&dev);
    cudaDeviceGetAttribute(&nsm, cudaDevAttrMultiProcessorCount, dev);

    const int SMEM_BYTES = 56192 * 4;   // 224,768 B
    cudaFuncSetAttribute(k_all, cudaFuncAttributeMaxDynamicSharedMemorySize, SMEM_BYTES);

    k_all<<<nsm, NT, SMEM_BYTES>>>(x, w_in, b_in, wg1, bg1, wg2, bg2, w_out, b_out, out);
}